// round 12
// baseline (speedup 1.0000x reference)
#include <cuda_runtime.h>
#include <cuda_bf16.h>
#include <math.h>

// Lowpass EMA scan: out[b,t,u] = (1-s[u])*x[b,t,u] + s[u]*prev
// Thread-per-chain + cp.async-staged input tiles (R8 skeleton: 128 blocks
// x 128 threads, TT=64, RING=6, AHEAD=4, issue-before-wait).
// R12: two-step carry lookahead. With 1 warp/SMSP the 4-cyc FMA carry
// chain (256 cyc/tile) has nothing to hide it; rewrite as
//   level_{t+2} = s^2*level_t + (s*c*x_{t+1} + c*x_{t+2})   (on-chain)
//   level_{t+1} = s*level_t + c*x_{t+1}                      (off-chain)
// -> one chain FMA per 2 outputs, halving serial exposure.

#define LP_B   16
#define LP_T   2048
#define LP_U   1024
#define TPB    128           // threads = chains per block
#define TT     64            // t per tile
#define NIT    (LP_T / TT)   // 32
#define RING   6
#define AHEAD  4
#define STAGE_FLOATS (TT * TPB)                 // 8192 floats = 32KB
#define SMEM_BYTES   (RING * STAGE_FLOATS * 4)  // 192KB

__device__ __forceinline__ void cp_async16(float* smem_dst, const float* gsrc) {
    unsigned sdst = (unsigned)__cvta_generic_to_shared(smem_dst);
    asm volatile("cp.async.cg.shared.global [%0], [%1], 16;\n"
                 :: "r"(sdst), "l"(gsrc));
}
__device__ __forceinline__ void cp_async_commit() {
    asm volatile("cp.async.commit_group;\n" ::: "memory");
}
template <int N>
__device__ __forceinline__ void cp_async_wait() {
    asm volatile("cp.async.wait_group %0;\n" :: "n"(N) : "memory");
}

__global__ void __launch_bounds__(TPB, 1)
lowpass_cpasync_kernel(const float* __restrict__ x,
                       const float* __restrict__ level_var,
                       const float* __restrict__ smoothing_var,
                       float* __restrict__ out)
{
    extern __shared__ float xs[];   // [RING][TT][TPB]

    const int tid = threadIdx.x;
    const int b   = blockIdx.x >> 3;          // 0..15
    const int u0  = (blockIdx.x & 7) << 7;    // 0,128,...,896
    const int u   = u0 + tid;

    const float sv = smoothing_var[u];
    const float s  = 1.0f / (1.0f + expf(-sv));
    const float c  = 1.0f - s;
    const float s2 = s * s;
    const float sc = s * c;
    float level    = level_var[u];

    const float* __restrict__ xb = x   + (size_t)b * LP_T * LP_U;
    float*       __restrict__ ob = out + (size_t)b * LP_T * LP_U;

    // Load mapping: row = 128 floats = 512B = 32 threads x 16B.
    const int lrow = tid >> 5;          // 0..3
    const int lcol = (tid & 31) << 2;   // 0,4,...,124

    // Prologue: tiles 0..AHEAD-1 in flight
#pragma unroll
    for (int p = 0; p < AHEAD; p++) {
        float* st = xs + p * STAGE_FLOATS;
#pragma unroll
        for (int k = 0; k < 16; k++) {
            const int r = lrow + 4 * k;
            cp_async16(st + r * TPB + lcol,
                       xb + (size_t)(p * TT + r) * LP_U + u0 + lcol);
        }
        cp_async_commit();
    }

    for (int it = 0; it < NIT; it++) {
        // Issue tile it+AHEAD first (slot held tile it-2: consumed, fenced)
        const int ls = it + AHEAD;
        if (ls < NIT) {
            float* st = xs + (ls % RING) * STAGE_FLOATS;
#pragma unroll
            for (int k = 0; k < 16; k++) {
                const int r = lrow + 4 * k;
                cp_async16(st + r * TPB + lcol,
                           xb + (size_t)(ls * TT + r) * LP_U + u0 + lcol);
            }
        }
        cp_async_commit();           // empty groups keep counts uniform

        cp_async_wait<AHEAD>();      // tile 'it' has landed (AHEAD pending max)
        __syncthreads();             // all slices visible; old slot free

        // Consume tile it: 2-step lookahead carry, coalesced streaming stores
        const float* tile = xs + (it % RING) * STAGE_FLOATS;
        float* op = ob + (size_t)(it * TT) * LP_U + u;
#pragma unroll
        for (int t = 0; t < TT; t += 2) {
            const float x1 = tile[t * TPB + tid];
            const float x2 = tile[(t + 1) * TPB + tid];
            const float cx1 = c * x1;
            const float a   = fmaf(sc, x1, c * x2);     // off-chain
            const float l1  = fmaf(s,  level, cx1);     // off-chain (odd out)
            level           = fmaf(s2, level, a);       // ON-chain (1 fma / 2 el)
            __stcs(op + (size_t)t * LP_U,       l1);
            __stcs(op + (size_t)(t + 1) * LP_U, level);
        }
    }
}

extern "C" void kernel_launch(void* const* d_in, const int* in_sizes, int n_in,
                              void* d_out, int out_size)
{
    const float* x         = (const float*)d_in[0];  // [B,T,U]
    const float* level_var = (const float*)d_in[1];  // [1,U]
    const float* smoothing = (const float*)d_in[2];  // [1,U]
    float* out             = (float*)d_out;          // [B,T,U]

    static int smem_set = 0;
    if (!smem_set) {
        cudaFuncSetAttribute(lowpass_cpasync_kernel,
                             cudaFuncAttributeMaxDynamicSharedMemorySize,
                             SMEM_BYTES);
        smem_set = 1;
    }

    const int blocks = LP_B * (LP_U / TPB);          // 128
    lowpass_cpasync_kernel<<<blocks, TPB, SMEM_BYTES>>>(x, level_var, smoothing, out);
}